// round 3
// baseline (speedup 1.0000x reference)
#include <cuda_runtime.h>

#define B_TOT   8192
#define T_STEPS 100
#define IN_DIM  32
#define H_DIM   32
#define HID     20
#define NRK     8

typedef unsigned long long u64;

// ---- packed f32x2 helpers (sm_103a) ----
__device__ __forceinline__ u64 pk(float lo, float hi) {
    u64 d; asm("mov.b64 %0, {%1, %2};" : "=l"(d) : "f"(lo), "f"(hi)); return d;
}
__device__ __forceinline__ void upk(u64 d, float& lo, float& hi) {
    asm("mov.b64 {%0, %1}, %2;" : "=f"(lo), "=f"(hi) : "l"(d));
}
__device__ __forceinline__ u64 pfma(u64 a, u64 b, u64 c) {
    u64 d; asm("fma.rn.f32x2 %0, %1, %2, %3;" : "=l"(d) : "l"(a), "l"(b), "l"(c)); return d;
}
__device__ __forceinline__ u64 pmul(u64 a, u64 b) {
    u64 d; asm("mul.rn.f32x2 %0, %1, %2;" : "=l"(d) : "l"(a), "l"(b)); return d;
}
__device__ __forceinline__ u64 padd(u64 a, u64 b) {
    u64 d; asm("add.rn.f32x2 %0, %1, %2;" : "=l"(d) : "l"(a), "l"(b)); return d;
}

// tanh(x) = 1 - 2/(exp(2x)+1); ~1e-7 abs err, exact at +-inf.
__device__ __forceinline__ float ftanh(float x) {
    float e = __expf(2.0f * x);
    return 1.0f - __fdividef(2.0f, e + 1.0f);
}

// One ODE-func eval, packed. zp[4] = 8 owned z-lanes as f32x2 pairs.
// Produces up[4] = tanh(relu(zc@W1z + c)@W2 + bf2) for owned 8 output lanes.
// Layer1 row j is fused straight into the layer2 accumulator update, so the
// relu activations never live in an array.
__device__ __forceinline__ void feval(const u64 zp[4], const float c[HID],
                                      const float* sW1z, const float* sW2,
                                      const float* sbf2, int base, u64 up[4])
{
    u64 a0 = pk(sbf2[base + 0], sbf2[base + 1]);
    u64 a1 = pk(sbf2[base + 2], sbf2[base + 3]);
    u64 a2 = pk(sbf2[base + 4], sbf2[base + 5]);
    u64 a3 = pk(sbf2[base + 6], sbf2[base + 7]);
#pragma unroll
    for (int j = 0; j < HID; ++j) {
        const ulonglong2* w1 = reinterpret_cast<const ulonglong2*>(sW1z + j * 32 + base);
        ulonglong2 wa = w1[0], wb = w1[1];
        u64 s2 = pmul(zp[0], wa.x);
        s2 = pfma(zp[1], wa.y, s2);
        s2 = pfma(zp[2], wb.x, s2);
        s2 = pfma(zp[3], wb.y, s2);
        float lo, hi; upk(s2, lo, hi);
        float s = lo + hi;
        s += __shfl_xor_sync(0xffffffffu, s, 1);
        s += __shfl_xor_sync(0xffffffffu, s, 2);
        float rj = fmaxf(s + c[j], 0.0f);
        u64 rr = pk(rj, rj);
        const ulonglong2* w2 = reinterpret_cast<const ulonglong2*>(sW2 + j * 32 + base);
        ulonglong2 va = w2[0], vb = w2[1];
        a0 = pfma(rr, va.x, a0);
        a1 = pfma(rr, va.y, a1);
        a2 = pfma(rr, vb.x, a2);
        a3 = pfma(rr, vb.y, a3);
    }
    float p, q;
    upk(a0, p, q); up[0] = pk(ftanh(p), ftanh(q));
    upk(a1, p, q); up[1] = pk(ftanh(p), ftanh(q));
    upk(a2, p, q); up[2] = pk(ftanh(p), ftanh(q));
    upk(a3, p, q); up[3] = pk(ftanh(p), ftanh(q));
}

__global__ __launch_bounds__(64, 8)
void latode_kernel(const float* __restrict__ dt,  const float* __restrict__ x,
                   const float* __restrict__ We1, const float* __restrict__ be1,
                   const float* __restrict__ We2, const float* __restrict__ be2,
                   const float* __restrict__ Wf1, const float* __restrict__ bf1,
                   const float* __restrict__ Wf2, const float* __restrict__ bf2,
                   const float* __restrict__ Wm1, const float* __restrict__ bm1,
                   const float* __restrict__ Wm2, const float* __restrict__ bm2,
                   float* __restrict__ out)
{
    __shared__ __align__(16) float sW1z[HID * 32];   // [j][i]  z-part of Wf1, transposed
    __shared__ __align__(16) float sW1x[HID * 32];   // [j][i]  x-part of Wf1, transposed
    __shared__ __align__(16) float sW2 [HID * 32];   // [j][o]  Wf2 natural
    __shared__ __align__(16) float sWe1T[10 * 32];   // [m][i]
    __shared__ __align__(16) float sWe2 [10 * 32];   // [m][o]
    __shared__ __align__(16) float sWm1T[10 * 32];   // [m][i]
    __shared__ float sbf1[HID], sbf2[32], sbe1[10], sbe2[32], sbm1[10], sWm2v[10], sbm2;

    const int tid = threadIdx.x;
    for (int idx = tid; idx < HID * 32; idx += blockDim.x) {
        int j = idx >> 5, i = idx & 31;
        sW1z[idx] = Wf1[i * HID + j];
        sW1x[idx] = Wf1[(32 + i) * HID + j];
        sW2[idx]  = Wf2[j * 32 + i];
    }
    for (int idx = tid; idx < 10 * 32; idx += blockDim.x) {
        int m = idx >> 5, i = idx & 31;
        sWe1T[idx] = We1[i * 10 + m];
        sWe2[idx]  = We2[m * 32 + i];
        sWm1T[idx] = Wm1[i * 10 + m];
    }
    if (tid < HID) sbf1[tid] = bf1[tid];
    if (tid < 32)  { sbf2[tid] = bf2[tid]; sbe2[tid] = be2[tid]; }
    if (tid < 10)  { sbe1[tid] = be1[tid]; sbm1[tid] = bm1[tid]; sWm2v[tid] = Wm2[tid]; }
    if (tid == 0)  sbm2 = bm2[0];
    __syncthreads();

    const int gt   = blockIdx.x * blockDim.x + tid;
    const int b    = gt >> 2;        // element id
    const int g    = gt & 3;         // sub-thread within element
    const int base = g * 8;          // owned lane window [base, base+8)

    const float hs = 1.0f / NRK;

    // ---- encoder: z0 = tanh(tanh(x0@We1+be1)@We2+be2) ----
    u64 xp[4];
    {
        const ulonglong2* q = reinterpret_cast<const ulonglong2*>(
            x + (size_t)b * T_STEPS * IN_DIM + base);
        ulonglong2 qa = q[0], qb = q[1];
        xp[0] = qa.x; xp[1] = qa.y; xp[2] = qb.x; xp[3] = qb.y;
    }
    float h10[10];
#pragma unroll
    for (int m = 0; m < 10; ++m) {
        const ulonglong2* w = reinterpret_cast<const ulonglong2*>(sWe1T + m * 32 + base);
        ulonglong2 wa = w[0], wb = w[1];
        u64 s2 = pmul(xp[0], wa.x);
        s2 = pfma(xp[1], wa.y, s2);
        s2 = pfma(xp[2], wb.x, s2);
        s2 = pfma(xp[3], wb.y, s2);
        float lo, hi; upk(s2, lo, hi);
        float s = lo + hi;
        s += __shfl_xor_sync(0xffffffffu, s, 1);
        s += __shfl_xor_sync(0xffffffffu, s, 2);
        h10[m] = ftanh(s + sbe1[m]);
    }
    u64 zp[4];
#pragma unroll
    for (int p = 0; p < 4; ++p) {
        float s0 = sbe2[base + 2 * p], s1 = sbe2[base + 2 * p + 1];
#pragma unroll
        for (int m = 0; m < 10; ++m) {
            s0 += h10[m] * sWe2[m * 32 + base + 2 * p];
            s1 += h10[m] * sWe2[m * 32 + base + 2 * p + 1];
        }
        zp[p] = pk(ftanh(s0), ftanh(s1));
    }

    // ---- time loop ----
    for (int t = 0; t < T_STEPS; ++t) {
        {   // x_i for this step
            const ulonglong2* q = reinterpret_cast<const ulonglong2*>(
                x + ((size_t)b * T_STEPS + t) * IN_DIM + base);
            ulonglong2 qa = q[0], qb = q[1];
            xp[0] = qa.x; xp[1] = qa.y; xp[2] = qb.x; xp[3] = qb.y;
        }
        const float2 dpair = *reinterpret_cast<const float2*>(dt + ((size_t)b * T_STEPS + t) * 2);
        const float sc = (dpair.y - dpair.x) * 0.01f;   // d * DT_SCALER
        const float ah = 0.5f * hs * sc;
        const float af = hs * sc;
        const float a6 = (hs / 6.0f) * sc;
        const u64 ahp = pk(ah, ah);
        const u64 afp = pk(af, af);
        const u64 a6p = pk(a6, a6);
        const u64 twp = pk(2.0f, 2.0f);

        // c[j] = (x_i @ W1x)[j] + bf1[j] — constant across the 32 f-evals of this step
        float c[HID];
#pragma unroll
        for (int j = 0; j < HID; ++j) {
            const ulonglong2* w = reinterpret_cast<const ulonglong2*>(sW1x + j * 32 + base);
            ulonglong2 wa = w[0], wb = w[1];
            u64 s2 = pmul(xp[0], wa.x);
            s2 = pfma(xp[1], wa.y, s2);
            s2 = pfma(xp[2], wb.x, s2);
            s2 = pfma(xp[3], wb.y, s2);
            float lo, hi; upk(s2, lo, hi);
            float s = lo + hi;
            s += __shfl_xor_sync(0xffffffffu, s, 1);
            s += __shfl_xor_sync(0xffffffffu, s, 2);
            c[j] = s + sbf1[j];
        }

        for (int rk = 0; rk < NRK; ++rk) {
            u64 up[4], sup[4], zcp[4];
            feval(zp, c, sW1z, sW2, sbf2, base, up);          // k1
#pragma unroll
            for (int p = 0; p < 4; ++p) { sup[p] = up[p]; zcp[p] = pfma(up[p], ahp, zp[p]); }
            feval(zcp, c, sW1z, sW2, sbf2, base, up);         // k2
#pragma unroll
            for (int p = 0; p < 4; ++p) { sup[p] = pfma(up[p], twp, sup[p]); zcp[p] = pfma(up[p], ahp, zp[p]); }
            feval(zcp, c, sW1z, sW2, sbf2, base, up);         // k3
#pragma unroll
            for (int p = 0; p < 4; ++p) { sup[p] = pfma(up[p], twp, sup[p]); zcp[p] = pfma(up[p], afp, zp[p]); }
            feval(zcp, c, sW1z, sW2, sbf2, base, up);         // k4
#pragma unroll
            for (int p = 0; p < 4; ++p) zp[p] = pfma(padd(sup[p], up[p]), a6p, zp[p]);
        }

        // mu = tanh(z@Wm1+bm1)@Wm2 + bm2
        float hm[10];
#pragma unroll
        for (int m = 0; m < 10; ++m) {
            const ulonglong2* w = reinterpret_cast<const ulonglong2*>(sWm1T + m * 32 + base);
            ulonglong2 wa = w[0], wb = w[1];
            u64 s2 = pmul(zp[0], wa.x);
            s2 = pfma(zp[1], wa.y, s2);
            s2 = pfma(zp[2], wb.x, s2);
            s2 = pfma(zp[3], wb.y, s2);
            float lo, hi; upk(s2, lo, hi);
            float s = lo + hi;
            s += __shfl_xor_sync(0xffffffffu, s, 1);
            s += __shfl_xor_sync(0xffffffffu, s, 2);
            hm[m] = ftanh(s + sbm1[m]);
        }
        float mu = sbm2;
#pragma unroll
        for (int m = 0; m < 10; ++m) mu += hm[m] * sWm2v[m];
        if (g == 0) out[(size_t)b * T_STEPS + t] = mu;
    }
}

extern "C" void kernel_launch(void* const* d_in, const int* in_sizes, int n_in,
                              void* d_out, int out_size)
{
    const float* dt  = (const float*)d_in[0];
    const float* x   = (const float*)d_in[1];
    const float* We1 = (const float*)d_in[2];
    const float* be1 = (const float*)d_in[3];
    const float* We2 = (const float*)d_in[4];
    const float* be2 = (const float*)d_in[5];
    const float* Wf1 = (const float*)d_in[6];
    const float* bf1 = (const float*)d_in[7];
    const float* Wf2 = (const float*)d_in[8];
    const float* bf2 = (const float*)d_in[9];
    const float* Wm1 = (const float*)d_in[10];
    const float* bm1 = (const float*)d_in[11];
    const float* Wm2 = (const float*)d_in[12];
    const float* bm2 = (const float*)d_in[13];
    float* out = (float*)d_out;

    // 4 threads per batch element; small blocks for even CTA->SM balance.
    dim3 block(64);
    dim3 grid((B_TOT * 4) / 64);   // 512 blocks
    latode_kernel<<<grid, block>>>(dt, x, We1, be1, We2, be2,
                                   Wf1, bf1, Wf2, bf2, Wm1, bm1, Wm2, bm2, out);
}

// round 5
// speedup vs baseline: 3.3214x; 3.3214x over previous
#include <cuda_runtime.h>

#define B_TOT   8192
#define T_STEPS 100
#define IN_DIM  32
#define H_DIM   32
#define HID     20
#define NRK     8

typedef unsigned long long u64;

// ---- packed f32x2 helpers (sm_103a) ----
__device__ __forceinline__ u64 pk(float lo, float hi) {
    u64 d; asm("mov.b64 %0, {%1, %2};" : "=l"(d) : "f"(lo), "f"(hi)); return d;
}
__device__ __forceinline__ void upk(u64 d, float& lo, float& hi) {
    asm("mov.b64 {%0, %1}, %2;" : "=f"(lo), "=f"(hi) : "l"(d));
}
__device__ __forceinline__ u64 pfma(u64 a, u64 b, u64 c) {
    u64 d; asm("fma.rn.f32x2 %0, %1, %2, %3;" : "=l"(d) : "l"(a), "l"(b), "l"(c)); return d;
}
__device__ __forceinline__ u64 pmul(u64 a, u64 b) {
    u64 d; asm("mul.rn.f32x2 %0, %1, %2;" : "=l"(d) : "l"(a), "l"(b)); return d;
}
__device__ __forceinline__ u64 padd(u64 a, u64 b) {
    u64 d; asm("add.rn.f32x2 %0, %1, %2;" : "=l"(d) : "l"(a), "l"(b)); return d;
}

// 8-lane segment sum via shuffle butterfly. Offsets 1,2,4 stay inside each
// 8-aligned lane group, so one full-mask instruction serves all 4 elements
// in the warp at once.
__device__ __forceinline__ float redux8(float v) {
    v += __shfl_xor_sync(0xffffffffu, v, 1);
    v += __shfl_xor_sync(0xffffffffu, v, 2);
    v += __shfl_xor_sync(0xffffffffu, v, 4);
    return v;
}

// exact-ish tanh: 1 - 2/(exp(2x)+1); ~1e-7 abs err. Used where accuracy matters.
__device__ __forceinline__ float ftanh(float x) {
    float e = __expf(2.0f * x);
    return 1.0f - __fdividef(2.0f, e + 1.0f);
}
// HW tanh (~5e-4 worst abs err) — used only inside the ODE func where the
// result is scaled by ~1e-4 before entering z.
__device__ __forceinline__ float tanha(float x) {
    float y; asm("tanh.approx.f32 %0, %1;" : "=f"(y) : "f"(x)); return y;
}

// One ODE-func eval. 8 threads per element; each owns 4 lanes (2 f32x2 pairs).
// up = tanh(relu(zc@W1z + c)@W2 + bf2) for the 4 owned output lanes.
__device__ __forceinline__ void feval(const u64 zp[2], const float c[HID],
                                      const float* sW1z, const float* sW2,
                                      u64 b01, u64 b23, int base, u64 up[2])
{
    u64 a0 = b01, a1 = b23;
#pragma unroll
    for (int j = 0; j < HID; ++j) {
        ulonglong2 w1 = *reinterpret_cast<const ulonglong2*>(sW1z + j * 32 + base);
        u64 s2 = pmul(zp[0], w1.x);
        s2 = pfma(zp[1], w1.y, s2);
        float lo, hi; upk(s2, lo, hi);
        float r = redux8(lo + hi) + c[j];
        r = fmaxf(r, 0.0f);
        u64 rr = pk(r, r);
        ulonglong2 w2 = *reinterpret_cast<const ulonglong2*>(sW2 + j * 32 + base);
        a0 = pfma(rr, w2.x, a0);
        a1 = pfma(rr, w2.y, a1);
    }
    float p, q;
    upk(a0, p, q); up[0] = pk(tanha(p), tanha(q));
    upk(a1, p, q); up[1] = pk(tanha(p), tanha(q));
}

__global__ __launch_bounds__(64)
void latode_kernel(const float* __restrict__ dt,  const float* __restrict__ x,
                   const float* __restrict__ We1, const float* __restrict__ be1,
                   const float* __restrict__ We2, const float* __restrict__ be2,
                   const float* __restrict__ Wf1, const float* __restrict__ bf1,
                   const float* __restrict__ Wf2, const float* __restrict__ bf2,
                   const float* __restrict__ Wm1, const float* __restrict__ bm1,
                   const float* __restrict__ Wm2, const float* __restrict__ bm2,
                   float* __restrict__ out)
{
    __shared__ __align__(16) float sW1z[HID * 32];   // [j][i]  z-part of Wf1, transposed
    __shared__ __align__(16) float sW1x[HID * 32];   // [j][i]  x-part of Wf1, transposed
    __shared__ __align__(16) float sW2 [HID * 32];   // [j][o]  Wf2 natural
    __shared__ __align__(16) float sWe1T[10 * 32];   // [m][i]
    __shared__ __align__(16) float sWe2 [10 * 32];   // [m][o]
    __shared__ __align__(16) float sWm1T[10 * 32];   // [m][i]
    __shared__ float sbf1[HID], sbf2[32], sbe1[10], sbe2[32], sbm1[10], sWm2v[10], sbm2;

    const int tid = threadIdx.x;
    for (int idx = tid; idx < HID * 32; idx += blockDim.x) {
        int j = idx >> 5, i = idx & 31;
        sW1z[idx] = Wf1[i * HID + j];
        sW1x[idx] = Wf1[(32 + i) * HID + j];
        sW2[idx]  = Wf2[j * 32 + i];
    }
    for (int idx = tid; idx < 10 * 32; idx += blockDim.x) {
        int m = idx >> 5, i = idx & 31;
        sWe1T[idx] = We1[i * 10 + m];
        sWe2[idx]  = We2[m * 32 + i];
        sWm1T[idx] = Wm1[i * 10 + m];
    }
    if (tid < HID) sbf1[tid] = bf1[tid];
    if (tid < 32)  { sbf2[tid] = bf2[tid]; sbe2[tid] = be2[tid]; }
    if (tid < 10)  { sbe1[tid] = be1[tid]; sbm1[tid] = bm1[tid]; sWm2v[tid] = Wm2[tid]; }
    if (tid == 0)  sbm2 = bm2[0];
    __syncthreads();

    const int gt   = blockIdx.x * blockDim.x + tid;
    const int b    = gt >> 3;        // element id
    const int g    = gt & 7;         // sub-thread within element
    const int base = g * 4;          // owned lane window [base, base+4)

    const float hs = 1.0f / NRK;

    // per-thread constant bias pairs for the owned ODE-func output lanes
    const u64 bf01 = pk(sbf2[base + 0], sbf2[base + 1]);
    const u64 bf23 = pk(sbf2[base + 2], sbf2[base + 3]);

    // ---- encoder: z0 = tanh(tanh(x0@We1+be1)@We2+be2) ----
    u64 xp0, xp1;
    {
        float4 xv = *reinterpret_cast<const float4*>(x + (size_t)b * T_STEPS * IN_DIM + base);
        xp0 = pk(xv.x, xv.y); xp1 = pk(xv.z, xv.w);
    }
    float h10[10];
#pragma unroll
    for (int m = 0; m < 10; ++m) {
        ulonglong2 w = *reinterpret_cast<const ulonglong2*>(sWe1T + m * 32 + base);
        u64 s2 = pmul(xp0, w.x);
        s2 = pfma(xp1, w.y, s2);
        float lo, hi; upk(s2, lo, hi);
        h10[m] = ftanh(redux8(lo + hi) + sbe1[m]);
    }
    u64 zp[2];
    {
        float s0 = sbe2[base + 0], s1 = sbe2[base + 1];
        float s2 = sbe2[base + 2], s3 = sbe2[base + 3];
#pragma unroll
        for (int m = 0; m < 10; ++m) {
            const float* w = sWe2 + m * 32 + base;
            s0 += h10[m] * w[0]; s1 += h10[m] * w[1];
            s2 += h10[m] * w[2]; s3 += h10[m] * w[3];
        }
        zp[0] = pk(ftanh(s0), ftanh(s1));
        zp[1] = pk(ftanh(s2), ftanh(s3));
    }

    // ---- time loop ----
#pragma unroll 1
    for (int t = 0; t < T_STEPS; ++t) {
        {
            float4 xv = *reinterpret_cast<const float4*>(
                x + ((size_t)b * T_STEPS + t) * IN_DIM + base);
            xp0 = pk(xv.x, xv.y); xp1 = pk(xv.z, xv.w);
        }
        const float2 dpair = *reinterpret_cast<const float2*>(dt + ((size_t)b * T_STEPS + t) * 2);
        const float sc = (dpair.y - dpair.x) * 0.01f;   // d * DT_SCALER
        const float ah = 0.5f * hs * sc;
        const float af = hs * sc;
        const float a6 = (hs / 6.0f) * sc;
        const u64 ahp = pk(ah, ah);
        const u64 afp = pk(af, af);
        const u64 a6p = pk(a6, a6);
        const u64 twp = pk(2.0f, 2.0f);

        // c[j] = (x_i @ W1x)[j] + bf1[j] — constant across the 32 f-evals this step
        float c[HID];
#pragma unroll
        for (int j = 0; j < HID; ++j) {
            ulonglong2 w = *reinterpret_cast<const ulonglong2*>(sW1x + j * 32 + base);
            u64 s2 = pmul(xp0, w.x);
            s2 = pfma(xp1, w.y, s2);
            float lo, hi; upk(s2, lo, hi);
            c[j] = redux8(lo + hi) + sbf1[j];
        }

#pragma unroll 1
        for (int rk = 0; rk < NRK; ++rk) {
            u64 up[2], sup[2], zcp[2];
            feval(zp, c, sW1z, sW2, bf01, bf23, base, up);     // k1
#pragma unroll
            for (int p = 0; p < 2; ++p) { sup[p] = up[p]; zcp[p] = pfma(up[p], ahp, zp[p]); }
            feval(zcp, c, sW1z, sW2, bf01, bf23, base, up);    // k2
#pragma unroll
            for (int p = 0; p < 2; ++p) { sup[p] = pfma(up[p], twp, sup[p]); zcp[p] = pfma(up[p], ahp, zp[p]); }
            feval(zcp, c, sW1z, sW2, bf01, bf23, base, up);    // k3
#pragma unroll
            for (int p = 0; p < 2; ++p) { sup[p] = pfma(up[p], twp, sup[p]); zcp[p] = pfma(up[p], afp, zp[p]); }
            feval(zcp, c, sW1z, sW2, bf01, bf23, base, up);    // k4
#pragma unroll
            for (int p = 0; p < 2; ++p) zp[p] = pfma(padd(sup[p], up[p]), a6p, zp[p]);
        }

        // mu = tanh(z@Wm1+bm1)@Wm2 + bm2  (exact tanh — direct path to output)
        float mu = sbm2;
#pragma unroll
        for (int m = 0; m < 10; ++m) {
            ulonglong2 w = *reinterpret_cast<const ulonglong2*>(sWm1T + m * 32 + base);
            u64 s2 = pmul(zp[0], w.x);
            s2 = pfma(zp[1], w.y, s2);
            float lo, hi; upk(s2, lo, hi);
            float hm = ftanh(redux8(lo + hi) + sbm1[m]);
            mu += hm * sWm2v[m];
        }
        if (g == 0) out[(size_t)b * T_STEPS + t] = mu;
    }
}

extern "C" void kernel_launch(void* const* d_in, const int* in_sizes, int n_in,
                              void* d_out, int out_size)
{
    const float* dt  = (const float*)d_in[0];
    const float* x   = (const float*)d_in[1];
    const float* We1 = (const float*)d_in[2];
    const float* be1 = (const float*)d_in[3];
    const float* We2 = (const float*)d_in[4];
    const float* be2 = (const float*)d_in[5];
    const float* Wf1 = (const float*)d_in[6];
    const float* bf1 = (const float*)d_in[7];
    const float* Wf2 = (const float*)d_in[8];
    const float* bf2 = (const float*)d_in[9];
    const float* Wm1 = (const float*)d_in[10];
    const float* bm1 = (const float*)d_in[11];
    const float* Wm2 = (const float*)d_in[12];
    const float* bm2 = (const float*)d_in[13];
    float* out = (float*)d_out;

    // 8 threads per batch element: 65536 threads, 1024 CTAs of 64 -> ~7 CTAs/SM
    dim3 block(64);
    dim3 grid((B_TOT * 8) / 64);
    latode_kernel<<<grid, block>>>(dt, x, We1, be1, We2, be2,
                                   Wf1, bf1, Wf2, bf2, Wm1, bm1, Wm2, bm2, out);
}